// round 5
// baseline (speedup 1.0000x reference)
#include <cuda_runtime.h>
#include <math.h>

#define LOG2E 1.4426950408889634f
typedef unsigned long long ull;

// ---------------- scratch (device globals; no allocation) ----------------
__device__ float g_XI  [128 * 4096];      // in_proj xi, planar [d][hw]
__device__ float g_Zp  [64 * 4096];       // z gate, planar [o][p]
__device__ float g_XCT [4096 * 128];      // conv+silu output, pixel-major [p][d]
__device__ float g_PROJT[4096 * 144];     // x_proj output, pixel-major [p][144]
__device__ float g_YN  [4096 * 1152];     // post-LN window features [p][pos*128+d]
__device__ float g_CORE[4 * 4096 * 64];   // addconv partials (split-k=4) [s][p][o]
__device__ float g_ALc [512 * 16];        // -exp(A_logs) * log2e
__device__ float g_WT  [1152 * 64];       // addconv_w transposed [pos*128+d][o]
__device__ float g_WoT [64 * 64];         // out_proj_w^T [c][o]
__device__ float g_WsT [64 * 64];         // skip_w^T [c][o]
__device__ int   g_fastA = 1;             // A has geometric structure (sticky)

// ---------------- helpers ----------------
__device__ __forceinline__ float ex2f_fast(float x) {
    float y; asm("ex2.approx.f32 %0, %1;" : "=f"(y) : "f"(x)); return y;
}
__device__ __forceinline__ float softplusf(float x) {
    return x > 15.f ? x : __logf(1.f + __expf(x));
}
__device__ __forceinline__ float siluf(float x) {
    return x / (1.f + __expf(-x));
}
__device__ __forceinline__ int refl(int v) {
    return v < 0 ? -v : (v > 63 ? 126 - v : v);
}
__device__ __forceinline__ ull pack2(float a, float b) {
    ull r; asm("mov.b64 %0, {%1,%2};" : "=l"(r) : "f"(a), "f"(b)); return r;
}
__device__ __forceinline__ void unpack2(ull v, float& a, float& b) {
    asm("mov.b64 {%0,%1}, %2;" : "=f"(a), "=f"(b) : "l"(v));
}
__device__ __forceinline__ ull fma2(ull a, ull b, ull c) {
    ull d; asm("fma.rn.f32x2 %0, %1, %2, %3;" : "=l"(d) : "l"(a), "l"(b), "l"(c)); return d;
}
__device__ __forceinline__ ull mul2(ull a, ull b) {
    ull d; asm("mul.rn.f32x2 %0, %1, %2;" : "=l"(d) : "l"(a), "l"(b)); return d;
}

// ---------------- K0: precompute ----------------
__global__ void k_pre(const float* __restrict__ A_logs,
                      const float* __restrict__ addconv_w,
                      const float* __restrict__ out_proj_w,
                      const float* __restrict__ skip_w) {
    int idx = blockIdx.x * 256 + threadIdx.x;
    if (idx < 73728) {
        int o = idx & 63; int rest = idx >> 6;
        int d = rest & 127; int pos = rest >> 7;
        g_WT[idx] = addconv_w[o * 1152 + d * 9 + pos];
    } else if (idx < 73728 + 8192) {
        int j = idx - 73728;
        float e = expf(A_logs[j]);
        g_ALc[j] = -e * LOG2E;
        int n = j & 15;
        float e0 = expf(A_logs[j & ~15]);
        if (fabsf(e - (float)(n + 1) * e0) > 1e-4f * fmaxf(e, 1e-6f))
            atomicAnd(&g_fastA, 0);
    } else if (idx < 73728 + 8192 + 4096) {
        int j = idx - 73728 - 8192;
        int o = j & 63, c = j >> 6;
        g_WoT[j] = out_proj_w[o * 64 + c];
    } else if (idx < 73728 + 8192 + 8192) {
        int j = idx - 73728 - 8192 - 4096;
        int o = j & 63, c = j >> 6;
        g_WsT[j] = skip_w[o * 64 + c];
    }
}

// ---------------- K1: fused LN + in_proj GEMM; grid (128, 6) ----------------
__global__ void __launch_bounds__(256) k_inproj(
    const float* __restrict__ x, const float* __restrict__ g,
    const float* __restrict__ b, const float* __restrict__ ipw) {
    __shared__ float xs[32][65];
    __shared__ float ws[64][34];
    const int tid = threadIdx.x;
    const int warp = tid >> 5, lane = tid & 31;
    const int p0 = blockIdx.x * 32;
    const int cg = blockIdx.y * 32;

    // inline LN: warp w handles px 4w..4w+3
    #pragma unroll
    for (int i = 0; i < 4; i++) {
        int px = warp * 4 + i;
        int p = p0 + px;
        float x0 = x[p * 64 + lane], x1 = x[p * 64 + lane + 32];
        float s = x0 + x1;
        #pragma unroll
        for (int off = 16; off > 0; off >>= 1) s += __shfl_xor_sync(0xffffffffu, s, off);
        float mu = s * (1.f / 64.f);
        float d0 = x0 - mu, d1 = x1 - mu;
        float q = d0 * d0 + d1 * d1;
        #pragma unroll
        for (int off = 16; off > 0; off >>= 1) q += __shfl_xor_sync(0xffffffffu, q, off);
        float rstd = rsqrtf(q * (1.f / 64.f) + 1e-5f);
        xs[px][lane]      = d0 * rstd * g[lane]      + b[lane];
        xs[px][lane + 32] = d1 * rstd * g[lane + 32] + b[lane + 32];
    }
    for (int e = tid; e < 2048; e += 256) {
        int cc = e >> 6, k = e & 63;
        ws[k][cc] = ipw[(cg + cc) * 64 + k];
    }
    __syncthreads();
    ull a0 = 0ull, a1 = 0ull;
    #pragma unroll
    for (int k = 0; k < 64; k++) {
        float xv = xs[lane][k];
        ull xp = pack2(xv, xv);
        a0 = fma2(xp, *(const ull*)&ws[k][4 * warp],     a0);
        a1 = fma2(xp, *(const ull*)&ws[k][4 * warp + 2], a1);
    }
    int p = p0 + lane;
    float r0, r1, r2, r3;
    unpack2(a0, r0, r1); unpack2(a1, r2, r3);
    int c = cg + 4 * warp;
    float rv[4] = {r0, r1, r2, r3};
    #pragma unroll
    for (int j = 0; j < 4; j++) {
        int cj = c + j;
        if (cj < 128) g_XI[cj * 4096 + p] = rv[j];
        else          g_Zp[(cj - 128) * 4096 + p] = rv[j];
    }
}

// ---------------- K2: depthwise 3x3 conv, smem row staging ----------------
__global__ void __launch_bounds__(256) k_conv(
    const float* __restrict__ cw, const float* __restrict__ cb) {
    __shared__ float srow[3][16][64];
    __shared__ float cwsm[16][9];
    __shared__ float cbsm[16];
    const int h  = blockIdx.x >> 3, dg = blockIdx.x & 7;
    const int tid = threadIdx.x;

    // stage 3 input rows x 16 ch x 64 w
    for (int e = tid; e < 3072; e += 256) {
        int r = e >> 10, dl = (e >> 6) & 15, ww = e & 63;
        int hh = h + r - 1;
        srow[r][dl][ww] = (hh < 0 || hh > 63) ? 0.f
            : g_XI[(dg * 16 + dl) * 4096 + hh * 64 + ww];
    }
    if (tid < 144) cwsm[tid / 9][tid % 9] = cw[(dg * 16 + tid / 9) * 9 + tid % 9];
    if (tid < 16)  cbsm[tid] = cb[dg * 16 + tid];
    __syncthreads();

    const int w = tid & 63, q = tid >> 6;
    float o[4];
    #pragma unroll
    for (int i = 0; i < 4; i++) {
        int dl = q * 4 + i;
        float acc = cbsm[dl];
        #pragma unroll
        for (int ki = 0; ki < 3; ki++) {
            if (w > 0)  acc = fmaf(cwsm[dl][ki * 3 + 0], srow[ki][dl][w - 1], acc);
                        acc = fmaf(cwsm[dl][ki * 3 + 1], srow[ki][dl][w],     acc);
            if (w < 63) acc = fmaf(cwsm[dl][ki * 3 + 2], srow[ki][dl][w + 1], acc);
        }
        o[i] = siluf(acc);
    }
    *(float4*)(g_XCT + (h * 64 + w) * 128 + dg * 16 + q * 4) =
        make_float4(o[0], o[1], o[2], o[3]);
}

// ---------------- K3: x_proj GEMM; grid (128, 4), 288 threads ----------------
__global__ void __launch_bounds__(288) k_xproj(const float* __restrict__ xpw) {
    __shared__ float xc[32][129];
    __shared__ float ws[128][38];
    const int tid = threadIdx.x;
    const int warp = tid >> 5, lane = tid & 31;
    const int p0 = blockIdx.x * 32;
    const int cg = blockIdx.y * 36;
    for (int e = tid; e < 4096; e += 288) {
        int px = e >> 7, k = e & 127;
        xc[px][k] = g_XCT[(p0 + px) * 128 + k];
    }
    for (int e = tid; e < 36 * 128; e += 288) {
        int cc = e >> 7, k = e & 127;
        ws[k][cc] = xpw[(cg + cc) * 128 + k];
    }
    __syncthreads();
    ull a0 = 0ull, a1 = 0ull;
    #pragma unroll 8
    for (int k = 0; k < 128; k++) {
        float xv = xc[lane][k];
        ull xp = pack2(xv, xv);
        a0 = fma2(xp, *(const ull*)&ws[k][4 * warp],     a0);
        a1 = fma2(xp, *(const ull*)&ws[k][4 * warp + 2], a1);
    }
    int pix = p0 + lane;
    float r0, r1, r2, r3;
    unpack2(a0, r0, r1); unpack2(a1, r2, r3);
    float* dst = g_PROJT + pix * 144 + cg + 4 * warp;
    dst[0] = r0; dst[1] = r1; dst[2] = r2; dst[3] = r3;
}

// ---------------- K4: selective scan, 2 ch/thread, 4 px/block ----------------
__global__ void __launch_bounds__(256) k_scan(
    const float* __restrict__ dtw, const float* __restrict__ dtb,
    const float* __restrict__ Dsp, const float* __restrict__ ong,
    const float* __restrict__ onb) {
    const int quad = threadIdx.x >> 6;     // pixel within block
    const int tid  = threadIdx.x & 63;
    const int p = blockIdx.x * 4 + quad;
    const int h = p >> 6, w = p & 63;
    const int d0 = tid, d1 = tid + 64;
    __shared__ __align__(16) float win[4][9][144];
    __shared__ float redS[4][9][2], redQ[4][9][2];
    __shared__ float mu_s[4][9], rs_s[4][9];

    const int fastA = g_fastA;

    for (int e = tid; e < 324; e += 64) {
        int pos = e / 36, c4 = e - pos * 36;
        int i = pos / 3, j = pos - 3 * (pos / 3);
        int hh = refl(h - 1 + i), ww = refl(w - 1 + j);
        ((float4*)win[quad][pos])[c4] =
            ((const float4*)(g_PROJT + (hh * 64 + ww) * 144))[c4];
    }
    float u9a[9], u9b[9];
    #pragma unroll
    for (int pos = 0; pos < 9; pos++) {
        int i = pos / 3, j = pos % 3;
        int hh = refl(h - 1 + i), ww = refl(w - 1 + j);
        const float* base = g_XCT + (hh * 64 + ww) * 128;
        u9a[pos] = base[d0];
        u9b[pos] = base[d1];
    }
    __syncthreads();

    constexpr int POS[4][9] = {
        {0,1,2,3,4,5,6,7,8},
        {0,3,6,1,4,7,2,5,8},
        {8,7,6,5,4,3,2,1,0},
        {8,5,2,7,4,1,6,3,0}};
    constexpr int PKB[4] = {0, 72, 36, 108};

    float ywa[9], ywb[9];
    #pragma unroll
    for (int t = 0; t < 9; t++) { ywa[t] = 0.f; ywb[t] = 0.f; }

    #pragma unroll
    for (int k = 0; k < 4; k++) {
        const int kda = k * 128 + d0, kdb = k * 128 + d1;
        float4 dwa = __ldg((const float4*)(dtw + kda * 4));
        float4 dwb = __ldg((const float4*)(dtw + kdb * 4));
        float dba = __ldg(dtb + kda), dbb = __ldg(dtb + kdb);
        float Dva = __ldg(Dsp + kda), Dvb = __ldg(Dsp + kdb);
        float AL0a = g_ALc[kda * 16], AL0b = g_ALc[kdb * 16];

        ull hpa[8], hpb[8];
        #pragma unroll
        for (int j = 0; j < 8; j++) { hpa[j] = 0ull; hpb[j] = 0ull; }

        #pragma unroll
        for (int l = 0; l < 9; l++) {
            const int pos = POS[k][l];
            float4 xr = *(const float4*)&win[quad][pos][PKB[k]];
            float sa = dba, sb = dbb;
            sa = fmaf(dwa.x, xr.x, sa); sa = fmaf(dwa.y, xr.y, sa);
            sa = fmaf(dwa.z, xr.z, sa); sa = fmaf(dwa.w, xr.w, sa);
            sb = fmaf(dwb.x, xr.x, sb); sb = fmaf(dwb.y, xr.y, sb);
            sb = fmaf(dwb.z, xr.z, sb); sb = fmaf(dwb.w, xr.w, sb);
            float dla = softplusf(sa), dlb = softplusf(sb);
            float dua = dla * u9a[pos], dub = dlb * u9b[pos];
            ull dupa = pack2(dua, dua), dupb = pack2(dub, dub);
            const ull* Bp = (const ull*)&win[quad][pos][PKB[k] + 4];
            const ull* Cp = (const ull*)&win[quad][pos][PKB[k] + 20];
            ull ypa = 0ull, ypb = 0ull;
            if (fastA) {
                float ra = ex2f_fast(dla * AL0a), rb = ex2f_fast(dlb * AL0b);
                float ra2 = ra * ra, rb2 = rb * rb;
                ull rra = pack2(ra2, ra2), rrb = pack2(rb2, rb2);
                ull dApa = pack2(ra, ra2), dApb = pack2(rb, rb2);
                #pragma unroll
                for (int j = 0; j < 8; j++) {
                    if (j) { dApa = mul2(dApa, rra); dApb = mul2(dApb, rrb); }
                    ull Bj = Bp[j], Cj = Cp[j];
                    hpa[j] = fma2(hpa[j], dApa, mul2(dupa, Bj));
                    hpb[j] = fma2(hpb[j], dApb, mul2(dupb, Bj));
                    ypa = fma2(hpa[j], Cj, ypa);
                    ypb = fma2(hpb[j], Cj, ypb);
                }
            } else {
                #pragma unroll
                for (int j = 0; j < 8; j++) {
                    float2 ala = *(const float2*)(g_ALc + kda * 16 + 2 * j);
                    float2 alb = *(const float2*)(g_ALc + kdb * 16 + 2 * j);
                    ull dApa = pack2(ex2f_fast(dla * ala.x), ex2f_fast(dla * ala.y));
                    ull dApb = pack2(ex2f_fast(dlb * alb.x), ex2f_fast(dlb * alb.y));
                    ull Bj = Bp[j], Cj = Cp[j];
                    hpa[j] = fma2(hpa[j], dApa, mul2(dupa, Bj));
                    hpb[j] = fma2(hpb[j], dApb, mul2(dupb, Bj));
                    ypa = fma2(hpa[j], Cj, ypa);
                    ypb = fma2(hpb[j], Cj, ypb);
                }
            }
            float ya0, ya1, yb0, yb1;
            unpack2(ypa, ya0, ya1); unpack2(ypb, yb0, yb1);
            ywa[pos] += fmaf(Dva, u9a[pos], ya0 + ya1);
            ywb[pos] += fmaf(Dvb, u9b[pos], yb0 + yb1);
        }
    }

    // per-position LayerNorm over 128 channels (2 warps x 2 ch/thread)
    const int wpx = tid >> 5, lane = tid & 31;
    #pragma unroll
    for (int pos = 0; pos < 9; pos++) {
        float v = ywa[pos] + ywb[pos];
        float q = ywa[pos] * ywa[pos] + ywb[pos] * ywb[pos];
        #pragma unroll
        for (int off = 16; off > 0; off >>= 1) {
            v += __shfl_xor_sync(0xffffffffu, v, off);
            q += __shfl_xor_sync(0xffffffffu, q, off);
        }
        if (lane == 0) { redS[quad][pos][wpx] = v; redQ[quad][pos][wpx] = q; }
    }
    __syncthreads();
    if (tid < 9) {
        float s = redS[quad][tid][0] + redS[quad][tid][1];
        float q = redQ[quad][tid][0] + redQ[quad][tid][1];
        float mu = s * (1.f / 128.f);
        float var = q * (1.f / 128.f) - mu * mu;
        mu_s[quad][tid] = mu;
        rs_s[quad][tid] = rsqrtf(var + 1e-5f);
    }
    __syncthreads();
    float ga = ong[d0], ba = onb[d0];
    float gb = ong[d1], bb = onb[d1];
    #pragma unroll
    for (int pos = 0; pos < 9; pos++) {
        float mu = mu_s[quad][pos], rs = rs_s[quad][pos];
        g_YN[p * 1152 + pos * 128 + d0] = (ywa[pos] - mu) * rs * ga + ba;
        g_YN[p * 1152 + pos * 128 + d1] = (ywb[pos] - mu) * rs * gb + bb;
    }
}

// ---------------- K5: addconv GEMM split-k=4 ----------------
__global__ void __launch_bounds__(256) k_addconv() {
    __shared__ float As[32][33];
    __shared__ float Bs[32][68];
    const int tid = threadIdx.x;
    const int warp = tid >> 5, lane = tid & 31;
    const int p0 = blockIdx.x * 32;
    const int split = blockIdx.y;
    const int kb = split * 288;
    ull acc[4] = {0ull, 0ull, 0ull, 0ull};
    for (int kt = 0; kt < 288; kt += 32) {
        __syncthreads();
        for (int e = tid; e < 1024; e += 256) {
            int px = e >> 5, k = e & 31;
            As[px][k] = g_YN[(p0 + px) * 1152 + kb + kt + k];
        }
        for (int e = tid; e < 2048; e += 256) {
            int k = e >> 6, c = e & 63;
            Bs[k][c] = g_WT[(kb + kt + k) * 64 + c];
        }
        __syncthreads();
        #pragma unroll
        for (int k = 0; k < 32; k++) {
            float a = As[lane][k];
            ull ap = pack2(a, a);
            #pragma unroll
            for (int j = 0; j < 4; j++)
                acc[j] = fma2(ap, *(const ull*)&Bs[k][8 * warp + 2 * j], acc[j]);
        }
    }
    int p = p0 + lane;
    float r0, r1, r2, r3, r4, r5, r6, r7;
    unpack2(acc[0], r0, r1); unpack2(acc[1], r2, r3);
    unpack2(acc[2], r4, r5); unpack2(acc[3], r6, r7);
    float* dst = g_CORE + split * 262144 + p * 64 + 8 * warp;
    *(float4*)dst       = make_float4(r0, r1, r2, r3);
    *(float4*)(dst + 4) = make_float4(r4, r5, r6, r7);
}

// ---------------- K6: gate + out_proj + skip (16 px/block) ----------------
__global__ void __launch_bounds__(256) k_epilogue(
    const float* __restrict__ x, const float* __restrict__ acb,
    const float* __restrict__ skip_b, float* __restrict__ out) {
    __shared__ float ov[16][65], xv[16][65], zsm[16][65];
    __shared__ float wo[64][65], ws[64][65];
    const int tid = threadIdx.x;
    const int o = tid & 63, pg = tid >> 6;
    const int p0 = blockIdx.x * 16;

    for (int e = tid; e < 4096; e += 256) {
        int c = e >> 6, oo = e & 63;
        wo[c][oo] = g_WoT[e];
        ws[c][oo] = g_WsT[e];
    }
    #pragma unroll
    for (int i = 0; i < 4; i++) {
        int idx = tid + i * 256;
        int px2 = idx & 15, o2 = idx >> 4;
        zsm[px2][o2] = g_Zp[o2 * 4096 + p0 + px2];
    }
    __syncthreads();
    float acbv = __ldg(acb + o);
    #pragma unroll
    for (int i = 0; i < 4; i++) {
        int px = pg * 4 + i;
        int p = p0 + px;
        float core = g_CORE[p * 64 + o] + g_CORE[262144 + p * 64 + o]
                   + g_CORE[524288 + p * 64 + o] + g_CORE[786432 + p * 64 + o] + acbv;
        ov[px][o] = core * siluf(zsm[px][o]);
        xv[px][o] = x[p * 64 + o];
    }
    __syncthreads();
    float acc[4];
    float sb = __ldg(skip_b + o);
    #pragma unroll
    for (int i = 0; i < 4; i++) acc[i] = sb;
    #pragma unroll 4
    for (int c = 0; c < 64; c++) {
        float wov = wo[c][o], wsv = ws[c][o];
        #pragma unroll
        for (int i = 0; i < 4; i++) {
            int px = pg * 4 + i;
            acc[i] = fmaf(ov[px][c], wov, acc[i]);
            acc[i] = fmaf(xv[px][c], wsv, acc[i]);
        }
    }
    #pragma unroll
    for (int i = 0; i < 4; i++)
        out[(p0 + pg * 4 + i) * 64 + o] = acc[i];
}

// ---------------- launch ----------------
extern "C" void kernel_launch(void* const* d_in, const int* in_sizes, int n_in,
                              void* d_out, int out_size) {
    const float* x          = (const float*)d_in[0];
    const float* in_norm_g  = (const float*)d_in[1];
    const float* in_norm_b  = (const float*)d_in[2];
    const float* in_proj_w  = (const float*)d_in[3];
    const float* conv_w     = (const float*)d_in[4];
    const float* conv_b     = (const float*)d_in[5];
    const float* x_proj_w   = (const float*)d_in[6];
    const float* dt_w       = (const float*)d_in[7];
    const float* dt_b       = (const float*)d_in[8];
    const float* A_logs     = (const float*)d_in[9];
    const float* Ds         = (const float*)d_in[10];
    const float* out_norm_g = (const float*)d_in[11];
    const float* out_norm_b = (const float*)d_in[12];
    const float* addconv_w  = (const float*)d_in[13];
    const float* addconv_b  = (const float*)d_in[14];
    const float* skip_w     = (const float*)d_in[15];
    const float* skip_b     = (const float*)d_in[16];
    const float* out_proj_w = (const float*)d_in[17];
    float* out = (float*)d_out;

    k_pre<<<352, 256>>>(A_logs, addconv_w, out_proj_w, skip_w);
    k_inproj<<<dim3(128, 6), 256>>>(x, in_norm_g, in_norm_b, in_proj_w);
    k_conv<<<512, 256>>>(conv_w, conv_b);
    k_xproj<<<dim3(128, 4), 288>>>(x_proj_w);
    k_scan<<<1024, 256>>>(dt_w, dt_b, Ds, out_norm_g, out_norm_b);
    k_addconv<<<dim3(128, 4), 256>>>();
    k_epilogue<<<256, 256>>>(x, addconv_b, skip_b, out);
}

// round 6
// speedup vs baseline: 1.1164x; 1.1164x over previous
#include <cuda_runtime.h>
#include <math.h>

#define LOG2E 1.4426950408889634f
typedef unsigned long long ull;

// ---------------- scratch (device globals; no allocation) ----------------
__device__ float g_XI  [128 * 4096];      // in_proj xi, planar [d][hw]
__device__ float g_Zp  [64 * 4096];       // z gate, planar [o][p]
__device__ float g_XCT [4096 * 128];      // conv+silu output, pixel-major [p][d]
__device__ float g_PROJT[4096 * 144];     // x_proj output, pixel-major [p][144]
__device__ float g_YN  [4096 * 1152];     // post-LN window features [p][pos*128+d]
__device__ float g_CORE[4 * 4096 * 64];   // addconv partials (split-k=4) [s][p][o]
__device__ float g_ALc [512 * 16];        // -exp(A_logs) * log2e
__device__ float g_WT  [1152 * 64];       // addconv_w transposed [pos*128+d][o]
__device__ float g_WoT [64 * 64];         // out_proj_w^T [c][o]
__device__ float g_WsT [64 * 64];         // skip_w^T [c][o]
__device__ int   g_fastA = 1;             // A has geometric structure (sticky)

// ---------------- helpers ----------------
__device__ __forceinline__ float ex2f_fast(float x) {
    float y; asm("ex2.approx.f32 %0, %1;" : "=f"(y) : "f"(x)); return y;
}
__device__ __forceinline__ float softplusf(float x) {
    return x > 15.f ? x : __logf(1.f + __expf(x));
}
__device__ __forceinline__ float siluf(float x) {
    return x / (1.f + __expf(-x));
}
__device__ __forceinline__ int refl(int v) {
    return v < 0 ? -v : (v > 63 ? 126 - v : v);
}
__device__ __forceinline__ ull pack2(float a, float b) {
    ull r; asm("mov.b64 %0, {%1,%2};" : "=l"(r) : "f"(a), "f"(b)); return r;
}
__device__ __forceinline__ void unpack2(ull v, float& a, float& b) {
    asm("mov.b64 {%0,%1}, %2;" : "=f"(a), "=f"(b) : "l"(v));
}
__device__ __forceinline__ ull fma2(ull a, ull b, ull c) {
    ull d; asm("fma.rn.f32x2 %0, %1, %2, %3;" : "=l"(d) : "l"(a), "l"(b), "l"(c)); return d;
}
__device__ __forceinline__ ull mul2(ull a, ull b) {
    ull d; asm("mul.rn.f32x2 %0, %1, %2;" : "=l"(d) : "l"(a), "l"(b)); return d;
}

// ---------------- K0: precompute ----------------
__global__ void k_pre(const float* __restrict__ A_logs,
                      const float* __restrict__ addconv_w,
                      const float* __restrict__ out_proj_w,
                      const float* __restrict__ skip_w) {
    int idx = blockIdx.x * 256 + threadIdx.x;
    if (idx < 73728) {
        int o = idx & 63; int rest = idx >> 6;
        int d = rest & 127; int pos = rest >> 7;
        g_WT[idx] = addconv_w[o * 1152 + d * 9 + pos];
    } else if (idx < 73728 + 8192) {
        int j = idx - 73728;
        float e = expf(A_logs[j]);
        g_ALc[j] = -e * LOG2E;
        int n = j & 15;
        float e0 = expf(A_logs[j & ~15]);
        if (fabsf(e - (float)(n + 1) * e0) > 1e-4f * fmaxf(e, 1e-6f))
            atomicAnd(&g_fastA, 0);
    } else if (idx < 73728 + 8192 + 4096) {
        int j = idx - 73728 - 8192;
        int o = j & 63, c = j >> 6;
        g_WoT[j] = out_proj_w[o * 64 + c];
    } else if (idx < 73728 + 8192 + 8192) {
        int j = idx - 73728 - 8192 - 4096;
        int o = j & 63, c = j >> 6;
        g_WsT[j] = skip_w[o * 64 + c];
    }
}

// ---------------- K1: fused LN + in_proj GEMM; grid (128, 6) ----------------
__global__ void __launch_bounds__(256) k_inproj(
    const float* __restrict__ x, const float* __restrict__ g,
    const float* __restrict__ b, const float* __restrict__ ipw) {
    __shared__ float xs[32][65];
    __shared__ float ws[64][34];
    const int tid = threadIdx.x;
    const int warp = tid >> 5, lane = tid & 31;
    const int p0 = blockIdx.x * 32;
    const int cg = blockIdx.y * 32;

    #pragma unroll
    for (int i = 0; i < 4; i++) {
        int px = warp * 4 + i;
        int p = p0 + px;
        float x0 = x[p * 64 + lane], x1 = x[p * 64 + lane + 32];
        float s = x0 + x1;
        #pragma unroll
        for (int off = 16; off > 0; off >>= 1) s += __shfl_xor_sync(0xffffffffu, s, off);
        float mu = s * (1.f / 64.f);
        float d0 = x0 - mu, d1 = x1 - mu;
        float q = d0 * d0 + d1 * d1;
        #pragma unroll
        for (int off = 16; off > 0; off >>= 1) q += __shfl_xor_sync(0xffffffffu, q, off);
        float rstd = rsqrtf(q * (1.f / 64.f) + 1e-5f);
        xs[px][lane]      = d0 * rstd * g[lane]      + b[lane];
        xs[px][lane + 32] = d1 * rstd * g[lane + 32] + b[lane + 32];
    }
    for (int e = tid; e < 2048; e += 256) {
        int cc = e >> 6, k = e & 63;
        ws[k][cc] = ipw[(cg + cc) * 64 + k];
    }
    __syncthreads();
    ull a0 = 0ull, a1 = 0ull;
    #pragma unroll
    for (int k = 0; k < 64; k++) {
        float xv = xs[lane][k];
        ull xp = pack2(xv, xv);
        a0 = fma2(xp, *(const ull*)&ws[k][4 * warp],     a0);
        a1 = fma2(xp, *(const ull*)&ws[k][4 * warp + 2], a1);
    }
    int p = p0 + lane;
    float r0, r1, r2, r3;
    unpack2(a0, r0, r1); unpack2(a1, r2, r3);
    int c = cg + 4 * warp;
    float rv[4] = {r0, r1, r2, r3};
    #pragma unroll
    for (int j = 0; j < 4; j++) {
        int cj = c + j;
        if (cj < 128) g_XI[cj * 4096 + p] = rv[j];
        else          g_Zp[(cj - 128) * 4096 + p] = rv[j];
    }
}

// ---------------- K2: depthwise 3x3 conv, smem row staging ----------------
__global__ void __launch_bounds__(256) k_conv(
    const float* __restrict__ cw, const float* __restrict__ cb) {
    __shared__ float srow[3][16][64];
    __shared__ float cwsm[16][9];
    __shared__ float cbsm[16];
    const int h  = blockIdx.x >> 3, dg = blockIdx.x & 7;
    const int tid = threadIdx.x;

    for (int e = tid; e < 3072; e += 256) {
        int r = e >> 10, dl = (e >> 6) & 15, ww = e & 63;
        int hh = h + r - 1;
        srow[r][dl][ww] = (hh < 0 || hh > 63) ? 0.f
            : g_XI[(dg * 16 + dl) * 4096 + hh * 64 + ww];
    }
    if (tid < 144) cwsm[tid / 9][tid % 9] = cw[(dg * 16 + tid / 9) * 9 + tid % 9];
    if (tid < 16)  cbsm[tid] = cb[dg * 16 + tid];
    __syncthreads();

    const int w = tid & 63, q = tid >> 6;
    float o[4];
    #pragma unroll
    for (int i = 0; i < 4; i++) {
        int dl = q * 4 + i;
        float acc = cbsm[dl];
        #pragma unroll
        for (int ki = 0; ki < 3; ki++) {
            if (w > 0)  acc = fmaf(cwsm[dl][ki * 3 + 0], srow[ki][dl][w - 1], acc);
                        acc = fmaf(cwsm[dl][ki * 3 + 1], srow[ki][dl][w],     acc);
            if (w < 63) acc = fmaf(cwsm[dl][ki * 3 + 2], srow[ki][dl][w + 1], acc);
        }
        o[i] = siluf(acc);
    }
    *(float4*)(g_XCT + (h * 64 + w) * 128 + dg * 16 + q * 4) =
        make_float4(o[0], o[1], o[2], o[3]);
}

// ---------------- K3: x_proj GEMM, pack-free px-paired; grid (64, 4), 288 thr ----------------
// block: 64 px x 36 c; thread: 4 px x 2 c (4 fma2/k, 4 LDS.64/k, no packs)
__global__ void __launch_bounds__(288) k_xproj(const float* __restrict__ xpw) {
    __shared__ __align__(16) float xcT[64][66];   // [k-local][px]
    __shared__ ull wsd[64][36];                   // duplicated weight pairs
    const int tid = threadIdx.x;
    const int pxg = tid & 15;        // 16 groups of 4 px
    const int cq  = tid >> 4;        // 18 groups of 2 c
    const int p0 = blockIdx.x * 64;
    const int cg = blockIdx.y * 36;

    ull acc00 = 0ull, acc01 = 0ull, acc10 = 0ull, acc11 = 0ull;

    for (int kb = 0; kb < 128; kb += 64) {
        __syncthreads();
        // stage xc transposed: coalesced over k
        for (int e = tid; e < 4096; e += 288) {
            int k = e & 63, px = e >> 6;
            xcT[k][px] = g_XCT[(p0 + px) * 128 + kb + k];
        }
        // stage duplicated weights: coalesced over k
        for (int e = tid; e < 2304; e += 288) {
            int k = e & 63, c = e >> 6;
            float wv = xpw[(cg + c) * 128 + kb + k];
            wsd[k][c] = pack2(wv, wv);
        }
        __syncthreads();
        #pragma unroll 4
        for (int k = 0; k < 64; k++) {
            ull xp0 = *(const ull*)&xcT[k][pxg * 4];
            ull xp1 = *(const ull*)&xcT[k][pxg * 4 + 2];
            ull w0 = wsd[k][cq * 2];
            ull w1 = wsd[k][cq * 2 + 1];
            acc00 = fma2(xp0, w0, acc00);
            acc01 = fma2(xp0, w1, acc01);
            acc10 = fma2(xp1, w0, acc10);
            acc11 = fma2(xp1, w1, acc11);
        }
    }
    float v[2][4];
    unpack2(acc00, v[0][0], v[0][1]);   // c0: px0, px1
    unpack2(acc10, v[0][2], v[0][3]);   // c0: px2, px3
    unpack2(acc01, v[1][0], v[1][1]);   // c1: px0, px1
    unpack2(acc11, v[1][2], v[1][3]);   // c1: px2, px3
    #pragma unroll
    for (int j = 0; j < 2; j++)
        #pragma unroll
        for (int i = 0; i < 4; i++)
            g_PROJT[(p0 + pxg * 4 + i) * 144 + cg + cq * 2 + j] = v[j][i];
}

// ---------------- K4: selective scan + combine + per-position LN (R4 version) ----------------
__global__ void __launch_bounds__(256) k_scan(
    const float* __restrict__ dtw, const float* __restrict__ dtb,
    const float* __restrict__ Dsp, const float* __restrict__ ong,
    const float* __restrict__ onb) {
    const int half = threadIdx.x >> 7;
    const int tid  = threadIdx.x & 127;
    const int p = blockIdx.x * 2 + half;
    const int h = p >> 6, w = p & 63;
    const int d = tid;
    __shared__ __align__(16) float win[2][9][144];
    __shared__ float redS[2][9][4], redQ[2][9][4];
    __shared__ float mu_s[2][9], rs_s[2][9];

    const int fastA = g_fastA;

    for (int e = tid; e < 9 * 36; e += 128) {
        int pos = e / 36, c4 = e - pos * 36;
        int i = pos / 3, j = pos - 3 * (pos / 3);
        int hh = refl(h - 1 + i), ww = refl(w - 1 + j);
        ((float4*)win[half][pos])[c4] =
            ((const float4*)(g_PROJT + (hh * 64 + ww) * 144))[c4];
    }
    float u9[9];
    #pragma unroll
    for (int pos = 0; pos < 9; pos++) {
        int i = pos / 3, j = pos % 3;
        int hh = refl(h - 1 + i), ww = refl(w - 1 + j);
        u9[pos] = g_XCT[(hh * 64 + ww) * 128 + d];
    }
    __syncthreads();

    constexpr int POS[4][9] = {
        {0,1,2,3,4,5,6,7,8},
        {0,3,6,1,4,7,2,5,8},
        {8,7,6,5,4,3,2,1,0},
        {8,5,2,7,4,1,6,3,0}};
    constexpr int PKB[4] = {0, 72, 36, 108};

    float yw[9];
    #pragma unroll
    for (int t = 0; t < 9; t++) yw[t] = 0.f;

    #pragma unroll
    for (int k = 0; k < 4; k++) {
        int kd = k * 128 + d;
        float4 dw = __ldg((const float4*)(dtw + kd * 4));
        float db = __ldg(dtb + kd);
        float Dv = __ldg(Dsp + kd);
        float AL0 = g_ALc[kd * 16];
        float delta[9];
        #pragma unroll
        for (int l = 0; l < 9; l++) {
            float4 xr = *(const float4*)&win[half][POS[k][l]][PKB[k]];
            float s = db;
            s = fmaf(dw.x, xr.x, s); s = fmaf(dw.y, xr.y, s);
            s = fmaf(dw.z, xr.z, s); s = fmaf(dw.w, xr.w, s);
            delta[l] = softplusf(s);
        }
        ull hp[8];
        #pragma unroll
        for (int j = 0; j < 8; j++) hp[j] = 0ull;
        #pragma unroll
        for (int l = 0; l < 9; l++) {
            const int pos = POS[k][l];
            float dl = delta[l];
            float du = dl * u9[pos];
            ull dup = pack2(du, du);
            const ull* Bp = (const ull*)&win[half][pos][PKB[k] + 4];
            const ull* Cp = (const ull*)&win[half][pos][PKB[k] + 20];
            ull yp = 0ull;
            if (fastA) {
                float r  = ex2f_fast(dl * AL0);
                float r2 = r * r;
                ull rr  = pack2(r2, r2);
                ull dAp = pack2(r, r2);
                #pragma unroll
                for (int j = 0; j < 8; j++) {
                    if (j) dAp = mul2(dAp, rr);
                    hp[j] = fma2(hp[j], dAp, mul2(dup, Bp[j]));
                    yp = fma2(hp[j], Cp[j], yp);
                }
            } else {
                #pragma unroll
                for (int j = 0; j < 8; j++) {
                    float2 al = *(const float2*)(g_ALc + kd * 16 + 2 * j);
                    ull dAp = pack2(ex2f_fast(dl * al.x), ex2f_fast(dl * al.y));
                    hp[j] = fma2(hp[j], dAp, mul2(dup, Bp[j]));
                    yp = fma2(hp[j], Cp[j], yp);
                }
            }
            float ylo, yhi; unpack2(yp, ylo, yhi);
            yw[pos] += fmaf(Dv, u9[pos], ylo + yhi);
        }
    }

    int warp = tid >> 5, lane = tid & 31;
    #pragma unroll
    for (int pos = 0; pos < 9; pos++) {
        float v = yw[pos], q = v * v;
        #pragma unroll
        for (int off = 16; off > 0; off >>= 1) {
            v += __shfl_xor_sync(0xffffffffu, v, off);
            q += __shfl_xor_sync(0xffffffffu, q, off);
        }
        if (lane == 0) { redS[half][pos][warp] = v; redQ[half][pos][warp] = q; }
    }
    __syncthreads();
    if (tid < 9) {
        float s = redS[half][tid][0] + redS[half][tid][1] + redS[half][tid][2] + redS[half][tid][3];
        float q = redQ[half][tid][0] + redQ[half][tid][1] + redQ[half][tid][2] + redQ[half][tid][3];
        float mu = s * (1.f / 128.f);
        float var = q * (1.f / 128.f) - mu * mu;
        mu_s[half][tid] = mu;
        rs_s[half][tid] = rsqrtf(var + 1e-5f);
    }
    __syncthreads();
    float gg = ong[d], bb = onb[d];
    #pragma unroll
    for (int pos = 0; pos < 9; pos++)
        g_YN[p * 1152 + pos * 128 + d] =
            (yw[pos] - mu_s[half][pos]) * rs_s[half][pos] * gg + bb;
}

// ---------------- K5: addconv GEMM split-k=4 ----------------
__global__ void __launch_bounds__(256) k_addconv() {
    __shared__ float As[32][33];
    __shared__ float Bs[32][68];
    const int tid = threadIdx.x;
    const int warp = tid >> 5, lane = tid & 31;
    const int p0 = blockIdx.x * 32;
    const int split = blockIdx.y;
    const int kb = split * 288;
    ull acc[4] = {0ull, 0ull, 0ull, 0ull};
    for (int kt = 0; kt < 288; kt += 32) {
        __syncthreads();
        for (int e = tid; e < 1024; e += 256) {
            int px = e >> 5, k = e & 31;
            As[px][k] = g_YN[(p0 + px) * 1152 + kb + kt + k];
        }
        for (int e = tid; e < 2048; e += 256) {
            int k = e >> 6, c = e & 63;
            Bs[k][c] = g_WT[(kb + kt + k) * 64 + c];
        }
        __syncthreads();
        #pragma unroll
        for (int k = 0; k < 32; k++) {
            float a = As[lane][k];
            ull ap = pack2(a, a);
            #pragma unroll
            for (int j = 0; j < 4; j++)
                acc[j] = fma2(ap, *(const ull*)&Bs[k][8 * warp + 2 * j], acc[j]);
        }
    }
    int p = p0 + lane;
    float r0, r1, r2, r3, r4, r5, r6, r7;
    unpack2(acc[0], r0, r1); unpack2(acc[1], r2, r3);
    unpack2(acc[2], r4, r5); unpack2(acc[3], r6, r7);
    float* dst = g_CORE + split * 262144 + p * 64 + 8 * warp;
    *(float4*)dst       = make_float4(r0, r1, r2, r3);
    *(float4*)(dst + 4) = make_float4(r4, r5, r6, r7);
}

// ---------------- K6: gate + out_proj + skip (16 px/block) ----------------
__global__ void __launch_bounds__(256) k_epilogue(
    const float* __restrict__ x, const float* __restrict__ acb,
    const float* __restrict__ skip_b, float* __restrict__ out) {
    __shared__ float ov[16][65], xv[16][65], zsm[16][65];
    __shared__ float wo[64][65], ws[64][65];
    const int tid = threadIdx.x;
    const int o = tid & 63, pg = tid >> 6;
    const int p0 = blockIdx.x * 16;

    for (int e = tid; e < 4096; e += 256) {
        int c = e >> 6, oo = e & 63;
        wo[c][oo] = g_WoT[e];
        ws[c][oo] = g_WsT[e];
    }
    #pragma unroll
    for (int i = 0; i < 4; i++) {
        int idx = tid + i * 256;
        int px2 = idx & 15, o2 = idx >> 4;
        zsm[px2][o2] = g_Zp[o2 * 4096 + p0 + px2];
    }
    __syncthreads();
    float acbv = __ldg(acb + o);
    #pragma unroll
    for (int i = 0; i < 4; i++) {
        int px = pg * 4 + i;
        int p = p0 + px;
        float core = g_CORE[p * 64 + o] + g_CORE[262144 + p * 64 + o]
                   + g_CORE[524288 + p * 64 + o] + g_CORE[786432 + p * 64 + o] + acbv;
        ov[px][o] = core * siluf(zsm[px][o]);
        xv[px][o] = x[p * 64 + o];
    }
    __syncthreads();
    float acc[4];
    float sb = __ldg(skip_b + o);
    #pragma unroll
    for (int i = 0; i < 4; i++) acc[i] = sb;
    #pragma unroll 4
    for (int c = 0; c < 64; c++) {
        float wov = wo[c][o], wsv = ws[c][o];
        #pragma unroll
        for (int i = 0; i < 4; i++) {
            int px = pg * 4 + i;
            acc[i] = fmaf(ov[px][c], wov, acc[i]);
            acc[i] = fmaf(xv[px][c], wsv, acc[i]);
        }
    }
    #pragma unroll
    for (int i = 0; i < 4; i++)
        out[(p0 + pg * 4 + i) * 64 + o] = acc[i];
}

// ---------------- launch ----------------
extern "C" void kernel_launch(void* const* d_in, const int* in_sizes, int n_in,
                              void* d_out, int out_size) {
    const float* x          = (const float*)d_in[0];
    const float* in_norm_g  = (const float*)d_in[1];
    const float* in_norm_b  = (const float*)d_in[2];
    const float* in_proj_w  = (const float*)d_in[3];
    const float* conv_w     = (const float*)d_in[4];
    const float* conv_b     = (const float*)d_in[5];
    const float* x_proj_w   = (const float*)d_in[6];
    const float* dt_w       = (const float*)d_in[7];
    const float* dt_b       = (const float*)d_in[8];
    const float* A_logs     = (const float*)d_in[9];
    const float* Ds         = (const float*)d_in[10];
    const float* out_norm_g = (const float*)d_in[11];
    const float* out_norm_b = (const float*)d_in[12];
    const float* addconv_w  = (const float*)d_in[13];
    const float* addconv_b  = (const float*)d_in[14];
    const float* skip_w     = (const float*)d_in[15];
    const float* skip_b     = (const float*)d_in[16];
    const float* out_proj_w = (const float*)d_in[17];
    float* out = (float*)d_out;

    k_pre<<<352, 256>>>(A_logs, addconv_w, out_proj_w, skip_w);
    k_inproj<<<dim3(128, 6), 256>>>(x, in_norm_g, in_norm_b, in_proj_w);
    k_conv<<<512, 256>>>(conv_w, conv_b);
    k_xproj<<<dim3(64, 4), 288>>>(x_proj_w);
    k_scan<<<2048, 256>>>(dt_w, dt_b, Ds, out_norm_g, out_norm_b);
    k_addconv<<<dim3(128, 4), 256>>>();
    k_epilogue<<<256, 256>>>(x, addconv_b, skip_b, out);
}